// round 7
// baseline (speedup 1.0000x reference)
#include <cuda_runtime.h>
#include <cuda_bf16.h>

#define TT 8
#define G  16
#define GG 256
#define DD 64
#define THRS 0.5f

// slot-spread accumulators: 0 wl, 1 pool, 2 obj, 3 pres, 4 flowsq, 5 sumzp, 6 sumflow
__device__ double g_slot[7][16];
__device__ unsigned g_ctr;

typedef unsigned long long u64;

__device__ __forceinline__ float wsum(float v) {
#pragma unroll
    for (int s = 16; s > 0; s >>= 1) v += __shfl_xor_sync(0xffffffffu, v, s);
    return v;
}

// ---- packed f32x2 helpers ----
__device__ __forceinline__ u64 mk2(unsigned lo, unsigned hi) {
    u64 r; asm("mov.b64 %0, {%1, %2};" : "=l"(r) : "r"(lo), "r"(hi)); return r;
}
__device__ __forceinline__ u64 mkf(float lo, float hi) {
    u64 r; asm("mov.b64 %0, {%1, %2};" : "=l"(r) : "f"(lo), "f"(hi)); return r;
}
__device__ __forceinline__ u64 ffma2(u64 a, u64 b, u64 c) {
    u64 r; asm("fma.rn.f32x2 %0, %1, %2, %3;" : "=l"(r) : "l"(a), "l"(b), "l"(c)); return r;
}
__device__ __forceinline__ float lohisum(u64 v) {
    unsigned a, b; asm("mov.b64 {%0, %1}, %2;" : "=r"(a), "=r"(b) : "l"(v));
    return __uint_as_float(a) + __uint_as_float(b);
}

// ---- bf16 helpers (bf16 = top 16 bits of fp32) ----
__device__ __forceinline__ unsigned pk2(float e0, float e1) {
    unsigned r;
    asm("cvt.rn.bf16x2.f32 %0, %1, %2;" : "=r"(r) : "f"(e1), "f"(e0));
    return r;  // e0 low half, e1 high half
}
__device__ __forceinline__ unsigned mulbf2(unsigned a, unsigned b) {
    unsigned r; asm("mul.rn.bf16x2 %0, %1, %2;" : "=r"(r) : "r"(a), "r"(b)); return r;
}
__device__ __forceinline__ unsigned maxbf2(unsigned a, unsigned b) {
    unsigned r; asm("max.bf16x2 %0, %1, %2;" : "=r"(r) : "r"(a), "r"(b)); return r;
}

// swizzled uint4 index within a [GG][8]-uint4 frame
#define SWZ(cell, q) (((cell) << 3) + ((q) ^ ((cell) & 7)))

#define SMEM_BYTES (3 * GG * 8 * 16 + 3 * GG * 4)  // 101,376 B -> 2 blocks/SM

// blocks [0,npair): pair blocks (512 thr = cell x half-D);
// blocks [npair, npair+nlight): image blocks (2 images each). Last block finalizes.
__global__ __launch_bounds__(512, 2) void fused_kernel(const float* __restrict__ zw,
                                                       const float* __restrict__ zp,
                                                       const float* __restrict__ fl,
                                                       const void* __restrict__ gs,
                                                       float* __restrict__ out,
                                                       int B, int npair, int nimg) {
    extern __shared__ char smraw[];
    __shared__ double rd[4];
    __shared__ unsigned isLast;
    int tid = threadIdx.x;
    int blk = blockIdx.x;
    int slot = blk & 15;
    if (tid < 4) rd[tid] = 0.0;

    if (blk < npair) {
        // ================= pair block =================
        uint4* s0b = (uint4*)smraw;            // frame t   bf16 [GG][8] swizzled
        uint4* s1b = s0b + GG * 8;             // frame t+1 bf16
        uint4* cmx = s1b + GG * 8;             // column-max of |s0|*p0, bf16
        float* p0s = (float*)(cmx + GG * 8);
        float* p1s = p0s + GG;
        float* n1s = p1s + GG;                 // reciprocal norms of frame t+1 cells

        int b = blk % B, t = blk / B;
        size_t f0 = (size_t)(t * B + b);
        size_t f1 = f0 + B;
        const float4* g0 = (const float4*)(zw + f0 * (GG * DD));
        const float4* g1 = (const float4*)(zw + f1 * (GG * DD));

        if (tid < GG) p0s[tid] = zp[f0 * GG + tid];
        else          p1s[tid - GG] = zp[f1 * GG + (tid - GG)];

        // coalesced load: exact fp32 z_what_loss (packed) + swizzled bf16 frames
        const u64 NEG1 = 0xBF800000BF800000ULL;
        u64 wl2 = 0ULL;
#pragma unroll
        for (int it = 0; it < 8; ++it) {
            int idx = it * 512 + tid;
            float4 a = g0[idx];
            float4 v = g1[idx];
            u64 a01 = mkf(a.x, a.y), a23 = mkf(a.z, a.w);
            u64 v01 = mkf(v.x, v.y), v23 = mkf(v.z, v.w);
            u64 d01 = ffma2(a01, NEG1, v01);
            u64 d23 = ffma2(a23, NEG1, v23);
            wl2 = ffma2(d01, d01, wl2);
            wl2 = ffma2(d23, d23, wl2);
            int cell = idx >> 4, d4 = idx & 15;
            int u2idx = SWZ(cell, d4 >> 1) * 2 + (d4 & 1);
            uint2 pa, pb;
            pa.x = pk2(a.x, a.y);  pa.y = pk2(a.z, a.w);
            pb.x = pk2(v.x, v.y);  pb.y = pk2(v.z, v.w);
            ((uint2*)s0b)[u2idx] = pa;
            ((uint2*)s1b)[u2idx] = pb;
        }
        float wl = lohisum(wl2);
        __syncthreads();

        int c = tid >> 1, h = tid & 1;
        int qb = h << 2;                        // this thread's q range: qb..qb+3
        int i = c >> 4, j = c & 15;
        int cb = c << 3, cx = c & 7;
        float p0c = p0s[c], p1c = p1s[c];

        // ---- colmax pass: column-direction max of |s0|*p0 (bf16) ----
        {
            int cL = (j > 0)  ? c - 1 : c;
            int cR = (j < 15) ? c + 1 : c;
            float pzm = (j > 0)  ? p0s[cL] : 0.f;
            float pzp = (j < 15) ? p0s[cR] : 0.f;
            unsigned zm = pk2(pzm, pzm), z0 = pk2(p0c, p0c), zp2 = pk2(pzp, pzp);
            int bL = cL << 3, xL = cL & 7, bR = cR << 3, xR = cR & 7;
#pragma unroll
            for (int q = 0; q < 4; ++q) {
                int qq = qb + q;
                uint4 um = s0b[bL + (qq ^ xL)];
                uint4 u0 = s0b[cb + (qq ^ cx)];
                uint4 up = s0b[bR + (qq ^ xR)];
                const unsigned* wm = (const unsigned*)&um;
                const unsigned* w0 = (const unsigned*)&u0;
                const unsigned* wp = (const unsigned*)&up;
                uint4 o;
                unsigned* ow = (unsigned*)&o;
#pragma unroll
                for (int w = 0; w < 4; ++w) {
                    unsigned m = mulbf2(w0[w] & 0x7FFF7FFFu, z0);
                    m = maxbf2(m, mulbf2(wm[w] & 0x7FFF7FFFu, zm));
                    m = maxbf2(m, mulbf2(wp[w] & 0x7FFF7FFFu, zp2));
                    ow[w] = m;
                }
                cmx[cb + (qq ^ cx)] = o;
            }
        }

        // wrapped neighbors (objects term) + pres mask
        int nb8[9];
        unsigned pmask = 0;
        {
            int k = 0;
#pragma unroll
            for (int di = -1; di <= 1; ++di)
#pragma unroll
                for (int dj = -1; dj <= 1; ++dj, ++k) {
                    int nc = ((i + di) & 15) * 16 + ((j + dj) & 15);
                    nb8[k] = nc << 3;
                    if (p1s[nc] > THRS) pmask |= (1u << k);
                }
        }
        __syncthreads();   // cmx ready

        // ---- loop A: prior norm + 9 wrapped dots (half-D) ----
        u64 dot2[9];
#pragma unroll
        for (int k = 0; k < 9; ++k) dot2[k] = 0ULL;
        u64 pn2 = 0ULL;
#pragma unroll
        for (int q = 0; q < 4; ++q) {
            int qq = qb + q;
            uint4 pu = s0b[cb + (qq ^ cx)];
            const unsigned* pw = (const unsigned*)&pu;
            u64 pr2[4];
#pragma unroll
            for (int w = 0; w < 4; ++w) {
                pr2[w] = mk2(pw[w] << 16, pw[w] & 0xFFFF0000u);   // exact pair
                pn2 = ffma2(pr2[w], pr2[w], pn2);
            }
#pragma unroll
            for (int k = 0; k < 9; ++k) {
                uint4 nu = s1b[nb8[k] + (qq ^ ((nb8[k] >> 3) & 7))];
                const unsigned* nw = (const unsigned*)&nu;
#pragma unroll
                for (int w = 0; w < 4; ++w)
                    dot2[k] = ffma2(pr2[w], mk2(nw[w] << 16, nw[w]), dot2[k]);
            }
        }

        // ---- loop B: row-max of colmax + pool partials (half-D) ----
        u64 cn2 = 0ULL, pd2 = 0ULL, na2 = 0ULL;
        {
            int ru  = (i > 0)  ? c - 16 : c;   // same &7 class as c
            int rdn = (i < 15) ? c + 16 : c;
            int bu = ru << 3, bd = rdn << 3;
#pragma unroll
            for (int q = 0; q < 4; ++q) {
                int qq = qb + q;
                int off = qq ^ cx;
                uint4 cu = s1b[cb + off];
                uint4 xu = cmx[bu + off];
                uint4 xc = cmx[cb + off];
                uint4 xd = cmx[bd + off];
                const unsigned* cw = (const unsigned*)&cu;
                const unsigned* au = (const unsigned*)&xu;
                const unsigned* ac = (const unsigned*)&xc;
                const unsigned* ad = (const unsigned*)&xd;
#pragma unroll
                for (int w = 0; w < 4; ++w) {
                    u64 ctrabs = mk2((cw[w] << 16) & 0x7FFF0000u, cw[w] & 0x7FFF0000u);
                    cn2 = ffma2(ctrabs, ctrabs, cn2);
                    unsigned mb = maxbf2(maxbf2(au[w], ac[w]), ad[w]);
                    u64 m2 = mk2(mb << 16, mb & 0xFFFF0000u);
                    pd2 = ffma2(m2, ctrabs, pd2);
                    na2 = ffma2(m2, m2, na2);
                }
            }
        }

        // combine the two half-D partials (adjacent lanes)
        float dotf[9];
#pragma unroll
        for (int k = 0; k < 9; ++k) {
            float d = lohisum(dot2[k]);
            dotf[k] = d + __shfl_xor_sync(0xffffffffu, d, 1);
        }
        float pn = lohisum(pn2); pn += __shfl_xor_sync(0xffffffffu, pn, 1);
        float cn = lohisum(cn2); cn += __shfl_xor_sync(0xffffffffu, cn, 1);
        float pd = lohisum(pd2); pd += __shfl_xor_sync(0xffffffffu, pd, 1);
        float na = lohisum(na2); na += __shfl_xor_sync(0xffffffffu, na, 1);

        if (h == 0) n1s[c] = fminf(rsqrtf(cn), 1e8f);   // 1/max(sqrt(cn),1e-8)
        __syncthreads();

        float obj = 0.f, pool = 0.f;
        if (h == 0) {
            float rpn = fminf(rsqrtf(pn), 1e8f);
            float ssum = 0.f, smax = -INFINITY;
#pragma unroll
            for (int k = 0; k < 9; ++k) {
                float s = dotf[k] * rpn * n1s[nb8[k] >> 3];
                if (pmask & (1u << k)) {
                    ssum += s;
                    smax = fmaxf(smax, s);
                }
            }
            if (p0c > THRS && pmask) obj = -5.0f * smax + ssum;
            float nb = fmaxf(p1c * sqrtf(cn), 1e-6f);
            float cosp = __fdividef(pd * p1c, fmaxf(sqrtf(na), 1e-6f) * nb);
            pool = -cosp * 0.5f * (p0c + p1c);
        }

        wl = wsum(wl); pool = wsum(pool); obj = wsum(obj);
        if ((tid & 31) == 0) {
            atomicAdd(&rd[0], (double)wl);
            atomicAdd(&rd[1], (double)pool);
            atomicAdd(&rd[2], (double)obj);
        }
        __syncthreads();
        if (tid == 0) {
            atomicAdd(&g_slot[0][slot], rd[0]);
            atomicAdd(&g_slot[1][slot], rd[1]);
            atomicAdd(&g_slot[2][slot], rd[2]);
        }
    } else {
        // ================= image block: 2 images, pres + flow =================
        float* sp = (float*)smraw;   // [2][GG]
        int half = tid >> 8;         // image within block
        int n = (blk - npair) * 2 + half;
        int c = tid & 255;

        float fsq = 0.f, zpc = 0.f, f = 0.f, pres = 0.f;
        if (n < nimg) {
            int t = n / B;
            zpc = zp[(size_t)n * GG + c];
            sp[half * GG + c] = zpc;
            __syncthreads();

            int i = c >> 4, j = c & 15;
            float mx = -INFINITY;
#pragma unroll
            for (int di = -1; di <= 1; ++di) {
                int ii = i + di;
                if (ii < 0 || ii >= G) continue;
#pragma unroll
                for (int dj = -1; dj <= 1; ++dj) {
                    int jj = j + dj;
                    if (jj < 0 || jj >= G) continue;
                    mx = fmaxf(mx, sp[half * GG + ii * G + jj]);
                }
            }

            f = fl[(size_t)n * GG + c];
            fsq = (f > 0.5f) ? (mx - f) * (mx - f) : 0.f;

            if (t >= 1 && t <= TT - 2) {
                float za = zp[(size_t)(n - B) * GG + c];
                float zb = zp[(size_t)(n + B) * GG + c];
                float dba = zb - za;
                float sim = 1.f - dba * dba;
                float d1 = zb - zpc, d2 = za - zpc;
                pres = sim * (d1 * d1 + d2 * d2);
            }
        } else {
            __syncthreads();
        }

        float v0 = wsum(fsq), v1 = wsum(zpc), v2 = wsum(f), v3 = wsum(pres);
        if ((tid & 31) == 0) {
            atomicAdd(&rd[0], (double)v0);
            atomicAdd(&rd[1], (double)v1);
            atomicAdd(&rd[2], (double)v2);
            atomicAdd(&rd[3], (double)v3);
        }
        __syncthreads();
        if (tid == 0) {
            atomicAdd(&g_slot[4][slot], rd[0]);
            atomicAdd(&g_slot[5][slot], rd[1]);
            atomicAdd(&g_slot[6][slot], rd[2]);
            atomicAdd(&g_slot[3][slot], rd[3]);
        }
    }

    // ================= last-block finalize =================
    if (tid == 0) {
        __threadfence();
        unsigned old = atomicAdd(&g_ctr, 1u);
        isLast = (old == gridDim.x - 1u) ? 1u : 0u;
    }
    __syncthreads();

    if (isLast && tid == 0) {
        __threadfence();
        double acc[7];
#pragma unroll
        for (int q = 0; q < 7; ++q) {
            double s = 0.0;
#pragma unroll
            for (int r = 0; r < 16; ++r) { s += g_slot[q][r]; g_slot[q][r] = 0.0; }
            acc[q] = s;
        }
        g_ctr = 0u;

        int gi = *(const int*)gs;
        double gstep = (gi < 0 || gi > 1000000000) ? (double)__int_as_float(gi) : (double)gi;

        double scale_obj = gstep / 200000.0;        if (scale_obj > 1.0) scale_obj = 1.0;
        double scale_flow = 1.0 - gstep / 100000.0; if (scale_flow < 0.0) scale_flow = 0.0;

        double hinge = acc[5] - acc[6];
        if (hinge < 0.0) hinge = 0.0;
        double flow_loss = acc[4] + 100.0 * hinge;

        double loss = acc[0]                        // z_what_loss (ADJ_W=1)
                    + acc[3]                        // z_pres_loss (PRES_W=1)
                    + acc[1]                        // pool (POOL_W=1)
                    + acc[2] * scale_obj * 10.0     // objects * OBJ_W
                    + flow_loss * scale_flow;       // FLOW_W=1
        out[0] = (float)loss;
    }
}

extern "C" void kernel_launch(void* const* d_in, const int* in_sizes, int n_in,
                              void* d_out, int out_size) {
    const float* zw = (const float*)d_in[0];
    const float* zp = (const float*)d_in[1];
    const float* fl = (const float*)d_in[2];
    const void*  gs = d_in[3];
    int B = in_sizes[0] / (TT * GG * DD);

    static int configured = 0;
    if (!configured) {
        cudaFuncSetAttribute(fused_kernel, cudaFuncAttributeMaxDynamicSharedMemorySize, SMEM_BYTES);
        configured = 1;
    }

    int npair = (TT - 1) * B;
    int nimg  = TT * B;
    int nlight = (nimg + 1) / 2;
    fused_kernel<<<npair + nlight, 512, SMEM_BYTES>>>(zw, zp, fl, gs, (float*)d_out, B, npair, nimg);
}

// round 9
// speedup vs baseline: 1.3636x; 1.3636x over previous
#include <cuda_runtime.h>
#include <cuda_bf16.h>

#define TT 8
#define G  16
#define GG 256
#define DD 64
#define THRS 0.5f

// slot-spread accumulators: 0 wl, 1 pool, 2 obj, 3 pres, 4 flowsq, 5 sumzp, 6 sumflow
__device__ double g_slot[7][16];
__device__ unsigned g_ctr;

typedef unsigned long long u64;

__device__ __forceinline__ float wsum(float v) {
#pragma unroll
    for (int s = 16; s > 0; s >>= 1) v += __shfl_xor_sync(0xffffffffu, v, s);
    return v;
}

// ---- packed f32x2 helpers ----
__device__ __forceinline__ u64 mk2(unsigned lo, unsigned hi) {
    u64 r; asm("mov.b64 %0, {%1, %2};" : "=l"(r) : "r"(lo), "r"(hi)); return r;
}
__device__ __forceinline__ u64 mkf(float lo, float hi) {
    u64 r; asm("mov.b64 %0, {%1, %2};" : "=l"(r) : "f"(lo), "f"(hi)); return r;
}
__device__ __forceinline__ u64 ffma2(u64 a, u64 b, u64 c) {
    u64 r; asm("fma.rn.f32x2 %0, %1, %2, %3;" : "=l"(r) : "l"(a), "l"(b), "l"(c)); return r;
}
__device__ __forceinline__ float lohisum(u64 v) {
    unsigned a, b; asm("mov.b64 {%0, %1}, %2;" : "=r"(a), "=r"(b) : "l"(v));
    return __uint_as_float(a) + __uint_as_float(b);
}

// ---- bf16 helpers (bf16 = top 16 bits of fp32) ----
__device__ __forceinline__ unsigned pk2(float e0, float e1) {
    unsigned r;
    asm("cvt.rn.bf16x2.f32 %0, %1, %2;" : "=r"(r) : "f"(e1), "f"(e0));
    return r;  // e0 low half, e1 high half
}
__device__ __forceinline__ unsigned mulbf2(unsigned a, unsigned b) {
    unsigned r; asm("mul.rn.bf16x2 %0, %1, %2;" : "=r"(r) : "r"(a), "r"(b)); return r;
}
__device__ __forceinline__ unsigned maxbf2(unsigned a, unsigned b) {
    unsigned r; asm("max.bf16x2 %0, %1, %2;" : "=r"(r) : "r"(a), "r"(b)); return r;
}

// swizzled uint4 index within a [GG][8]-uint4 frame (zero padding, conflict-free)
#define SWZ(cell, q) (((cell) << 3) + ((q) ^ ((cell) & 7)))

// s0 frame gets one extra all-zero row (cell index GG) for clamped pool neighbors
#define S0_ROWS (GG + 1)
#define SMEM_BYTES ((S0_ROWS * 8 + GG * 8) * 16 + 3 * GG * 4)  // 68,736 B -> 3 blocks/SM

// blocks [0,npair): pair blocks (thread = cell); [npair,npair+nimg): image blocks.
__global__ __launch_bounds__(256, 3) void fused_kernel(const float* __restrict__ zw,
                                                       const float* __restrict__ zp,
                                                       const float* __restrict__ fl,
                                                       const void* __restrict__ gs,
                                                       float* __restrict__ out,
                                                       int B, int npair, int nimg) {
    extern __shared__ char smraw[];
    __shared__ double rd[4];
    __shared__ unsigned isLast;
    int tid = threadIdx.x;
    int blk = blockIdx.x;
    int slot = blk & 15;
    if (tid < 4) rd[tid] = 0.0;

    if (blk < npair) {
        // ================= pair block: wl / pool / objects =================
        uint4* s0b = (uint4*)smraw;            // frame t bf16 [GG+1][8]; row GG = zeros
        uint4* s1b = s0b + S0_ROWS * 8;        // frame t+1 bf16 [GG][8]
        float* p0s = (float*)(s1b + GG * 8);
        float* p1s = p0s + GG;
        float* n1s = p1s + GG;                 // reciprocal norms of frame t+1 cells

        int b = blk % B, t = blk / B;
        size_t f0 = (size_t)(t * B + b);
        size_t f1 = f0 + B;
        const float4* g0 = (const float4*)(zw + f0 * (GG * DD));
        const float4* g1 = (const float4*)(zw + f1 * (GG * DD));

        p0s[tid] = zp[f0 * GG + tid];
        p1s[tid] = zp[f1 * GG + tid];
        if (tid < 32) ((unsigned*)(s0b + GG * 8))[tid] = 0u;   // zero row

        // coalesced load: exact fp32 z_what_loss (packed) + swizzled bf16 frames
        const u64 NEG1 = 0xBF800000BF800000ULL;
        u64 wl2 = 0ULL;
#pragma unroll
        for (int it = 0; it < 16; ++it) {
            int idx = it * 256 + tid;
            float4 a = g0[idx];
            float4 v = g1[idx];
            u64 d01 = ffma2(mkf(a.x, a.y), NEG1, mkf(v.x, v.y));
            u64 d23 = ffma2(mkf(a.z, a.w), NEG1, mkf(v.z, v.w));
            wl2 = ffma2(d01, d01, wl2);
            wl2 = ffma2(d23, d23, wl2);
            int cell = idx >> 4, d4 = idx & 15;
            int u2idx = SWZ(cell, d4 >> 1) * 2 + (d4 & 1);
            uint2 pa, pb;
            pa.x = pk2(a.x, a.y);  pa.y = pk2(a.z, a.w);
            pb.x = pk2(v.x, v.y);  pb.y = pk2(v.z, v.w);
            ((uint2*)s0b)[u2idx] = pa;
            ((uint2*)s1b)[u2idx] = pb;
        }
        float wl = lohisum(wl2);
        __syncthreads();

        int c = tid;
        int i = c >> 4, j = c & 15;
        int cb = c << 3, cx = c & 7;
        float p0c = p0s[c], p1c = p1s[c];
        unsigned z0 = pk2(p0c, p0c);

        // wrapped neighbor indexing (objects term, frame t+1) + pres mask
        int nb8[9];
        unsigned pmask = 0;
        {
            int k = 0;
#pragma unroll
            for (int di = -1; di <= 1; ++di)
#pragma unroll
                for (int dj = -1; dj <= 1; ++dj, ++k) {
                    int nc = ((i + di) & 15) * 16 + ((j + dj) & 15);
                    nb8[k] = nc << 3;
                    if (p1s[nc] > THRS) pmask |= (1u << k);
                }
        }

        // ---- loop A: prior norm + 9 wrapped dots + in-place transform ----
        // after this loop, s0[c] holds |s0[c]|*p0[c] in bf16 (own row only)
        u64 dot2[9];
#pragma unroll
        for (int k = 0; k < 9; ++k) dot2[k] = 0ULL;
        u64 pn2 = 0ULL;
#pragma unroll
        for (int q = 0; q < 8; ++q) {
            int off = q ^ cx;
            uint4 pu = s0b[cb + off];
            const unsigned* pw = (const unsigned*)&pu;
            u64 pr2[4];
#pragma unroll
            for (int w = 0; w < 4; ++w) {
                pr2[w] = mk2(pw[w] << 16, pw[w] & 0xFFFF0000u);   // exact pair
                pn2 = ffma2(pr2[w], pr2[w], pn2);
            }
#pragma unroll
            for (int k = 0; k < 9; ++k) {
                uint4 nu = s1b[nb8[k] + (q ^ ((nb8[k] >> 3) & 7))];
                const unsigned* nw = (const unsigned*)&nu;
#pragma unroll
                for (int w = 0; w < 4; ++w)
                    dot2[k] = ffma2(pr2[w], mk2(nw[w] << 16, nw[w]), dot2[k]);
            }
            uint4 tw;
            tw.x = mulbf2(pw[0] & 0x7FFF7FFFu, z0);
            tw.y = mulbf2(pw[1] & 0x7FFF7FFFu, z0);
            tw.z = mulbf2(pw[2] & 0x7FFF7FFFu, z0);
            tw.w = mulbf2(pw[3] & 0x7FFF7FFFu, z0);
            s0b[cb + off] = tw;
        }
        float pn = lohisum(pn2);
        float dotf[9];
#pragma unroll
        for (int k = 0; k < 9; ++k) dotf[k] = lohisum(dot2[k]);
        __syncthreads();   // all rows transformed

        // clamped pool indexing: out-of-grid -> zero row (cell GG)
        int cb8[9];
        {
            int k = 0;
#pragma unroll
            for (int di = -1; di <= 1; ++di)
#pragma unroll
                for (int dj = -1; dj <= 1; ++dj, ++k) {
                    int ii = i + di, jj = j + dj;
                    bool inb = (ii >= 0 && ii < G && jj >= 0 && jj < G);
                    cb8[k] = (inb ? (ii * 16 + jj) : GG) << 3;
                }
        }

        // ---- loop B: 3x3 max of transformed s0 + pool partials ----
        u64 cn2 = 0ULL, pd2 = 0ULL, na2 = 0ULL;
#pragma unroll
        for (int q = 0; q < 8; ++q) {
            uint4 cu = s1b[cb + (q ^ cx)];
            const unsigned* cw = (const unsigned*)&cu;
            u64 ctrabs[4];
#pragma unroll
            for (int w = 0; w < 4; ++w) {
                ctrabs[w] = mk2((cw[w] << 16) & 0x7FFF0000u, cw[w] & 0x7FFF0000u);
                cn2 = ffma2(ctrabs[w], ctrabs[w], cn2);
            }
            unsigned mb0 = 0u, mb1 = 0u, mb2 = 0u, mb3 = 0u;
#pragma unroll
            for (int k = 0; k < 9; ++k) {
                uint4 su = s0b[cb8[k] + (q ^ ((cb8[k] >> 3) & 7))];
                mb0 = maxbf2(mb0, su.x);
                mb1 = maxbf2(mb1, su.y);
                mb2 = maxbf2(mb2, su.z);
                mb3 = maxbf2(mb3, su.w);
            }
            unsigned mb[4] = {mb0, mb1, mb2, mb3};
#pragma unroll
            for (int w = 0; w < 4; ++w) {
                u64 m2 = mk2(mb[w] << 16, mb[w] & 0xFFFF0000u);
                pd2 = ffma2(m2, ctrabs[w], pd2);
                na2 = ffma2(m2, m2, na2);
            }
        }
        float cn = lohisum(cn2), pd = lohisum(pd2), na = lohisum(na2);

        n1s[c] = fminf(rsqrtf(cn), 1e8f);    // 1/max(sqrt(cn),1e-8)
        __syncthreads();

        float rpn = fminf(rsqrtf(pn), 1e8f);
        float ssum = 0.f, smax = -INFINITY;
#pragma unroll
        for (int k = 0; k < 9; ++k) {
            float s = dotf[k] * rpn * n1s[nb8[k] >> 3];
            if (pmask & (1u << k)) {
                ssum += s;
                smax = fmaxf(smax, s);
            }
        }
        float obj = (p0c > THRS && pmask) ? (-5.0f * smax + ssum) : 0.f;
        float nb = fmaxf(p1c * sqrtf(cn), 1e-6f);
        float cosp = __fdividef(pd * p1c, fmaxf(sqrtf(na), 1e-6f) * nb);
        float pool = -cosp * 0.5f * (p0c + p1c);

        wl = wsum(wl); pool = wsum(pool); obj = wsum(obj);
        if ((tid & 31) == 0) {
            atomicAdd(&rd[0], (double)wl);
            atomicAdd(&rd[1], (double)pool);
            atomicAdd(&rd[2], (double)obj);
        }
        __syncthreads();
        if (tid == 0) {
            atomicAdd(&g_slot[0][slot], rd[0]);
            atomicAdd(&g_slot[1][slot], rd[1]);
            atomicAdd(&g_slot[2][slot], rd[2]);
        }
    } else {
        // ================= image block: pres triples + flow term =================
        float* sp = (float*)smraw;
        int n = blk - npair;
        int t = n / B;
        int c = tid;

        float zpc = zp[(size_t)n * GG + c];
        sp[c] = zpc;
        __syncthreads();

        int i = c >> 4, j = c & 15;
        float mx = -INFINITY;
#pragma unroll
        for (int di = -1; di <= 1; ++di) {
            int ii = i + di;
            if (ii < 0 || ii >= G) continue;
#pragma unroll
            for (int dj = -1; dj <= 1; ++dj) {
                int jj = j + dj;
                if (jj < 0 || jj >= G) continue;
                mx = fmaxf(mx, sp[ii * G + jj]);
            }
        }

        float f = fl[(size_t)n * GG + c];
        float fsq = (f > 0.5f) ? (mx - f) * (mx - f) : 0.f;

        float pres = 0.f;
        if (t >= 1 && t <= TT - 2) {
            float za = zp[(size_t)(n - B) * GG + c];
            float zb = zp[(size_t)(n + B) * GG + c];
            float dba = zb - za;
            float sim = 1.f - dba * dba;
            float d1 = zb - zpc, d2 = za - zpc;
            pres += sim * (d1 * d1 + d2 * d2);
        }

        float v0 = wsum(fsq), v1 = wsum(zpc), v2 = wsum(f), v3 = wsum(pres);
        if ((c & 31) == 0) {
            atomicAdd(&rd[0], (double)v0);
            atomicAdd(&rd[1], (double)v1);
            atomicAdd(&rd[2], (double)v2);
            atomicAdd(&rd[3], (double)v3);
        }
        __syncthreads();
        if (tid == 0) {
            atomicAdd(&g_slot[4][slot], rd[0]);
            atomicAdd(&g_slot[5][slot], rd[1]);
            atomicAdd(&g_slot[6][slot], rd[2]);
            atomicAdd(&g_slot[3][slot], rd[3]);
        }
    }

    // ================= last-block finalize =================
    if (tid == 0) {
        __threadfence();
        unsigned old = atomicAdd(&g_ctr, 1u);
        isLast = (old == (unsigned)(npair + nimg) - 1u) ? 1u : 0u;
    }
    __syncthreads();

    if (isLast && tid == 0) {
        __threadfence();
        double acc[7];
#pragma unroll
        for (int q = 0; q < 7; ++q) {
            double s = 0.0;
#pragma unroll
            for (int r = 0; r < 16; ++r) { s += g_slot[q][r]; g_slot[q][r] = 0.0; }
            acc[q] = s;
        }
        g_ctr = 0u;

        int gi = *(const int*)gs;
        double gstep = (gi < 0 || gi > 1000000000) ? (double)__int_as_float(gi) : (double)gi;

        double scale_obj = gstep / 200000.0;        if (scale_obj > 1.0) scale_obj = 1.0;
        double scale_flow = 1.0 - gstep / 100000.0; if (scale_flow < 0.0) scale_flow = 0.0;

        double hinge = acc[5] - acc[6];
        if (hinge < 0.0) hinge = 0.0;
        double flow_loss = acc[4] + 100.0 * hinge;

        double loss = acc[0]                        // z_what_loss (ADJ_W=1)
                    + acc[3]                        // z_pres_loss (PRES_W=1)
                    + acc[1]                        // pool (POOL_W=1)
                    + acc[2] * scale_obj * 10.0     // objects * OBJ_W
                    + flow_loss * scale_flow;       // FLOW_W=1
        out[0] = (float)loss;
    }
}

extern "C" void kernel_launch(void* const* d_in, const int* in_sizes, int n_in,
                              void* d_out, int out_size) {
    const float* zw = (const float*)d_in[0];
    const float* zp = (const float*)d_in[1];
    const float* fl = (const float*)d_in[2];
    const void*  gs = d_in[3];
    int B = in_sizes[0] / (TT * GG * DD);

    static int configured = 0;
    if (!configured) {
        cudaFuncSetAttribute(fused_kernel, cudaFuncAttributeMaxDynamicSharedMemorySize, SMEM_BYTES);
        configured = 1;
    }

    int npair = (TT - 1) * B;
    int nimg  = TT * B;
    fused_kernel<<<npair + nimg, 256, SMEM_BYTES>>>(zw, zp, fl, gs, (float*)d_out, B, npair, nimg);
}